// round 6
// baseline (speedup 1.0000x reference)
#include <cuda_runtime.h>

#define NB   32
#define CINC 64
#define COUTC 128
#define TDIM 256
#define VV   25
#define ICC  32
#define EPSB 1e-5f

// ---------------- scratch (device globals, no allocation) ----------------
__device__ float g_h[(size_t)NB*COUTC*TDIM*VV];   // BN1+ReLU activations (temporal-conv input)
__device__ float g_r[(size_t)NB*COUTC*TDIM*VV];   // residual branch (BN'd) + all epilogue constants
__device__ float g_xbar[NB*CINC*VV];              // mean over T of x
__device__ float g_p[NB*ICC*VV];                  // softmax(-x2) probabilities
__device__ float g_w3fT[CINC*COUTC];              // w3 * s1, transposed [c][o]
__device__ float g_w4fT[CINC*COUTC];              // w4 * s1, transposed
__device__ float g_wr2T[CINC*COUTC];              // wr * sr, transposed
__device__ float g_b3f[COUTC];
__device__ float g_b4f[COUTC];
__device__ float g_h1[COUTC];
__device__ float g_Cc[COUTC];                     // br*sr+hr + bt*s2+h2
__device__ float g_wt2[COUTC*COUTC*9];            // wt * s2

// ---------------- K0: BN folding ----------------
__global__ void k_fold(const float* __restrict__ w3, const float* __restrict__ b3,
                       const float* __restrict__ w4, const float* __restrict__ b4,
                       const float* __restrict__ bn1_g, const float* __restrict__ bn1_b,
                       const float* __restrict__ bn1_m, const float* __restrict__ bn1_v,
                       const float* __restrict__ wt,  const float* __restrict__ bt,
                       const float* __restrict__ bn2_g, const float* __restrict__ bn2_b,
                       const float* __restrict__ bn2_m, const float* __restrict__ bn2_v,
                       const float* __restrict__ wr,  const float* __restrict__ br,
                       const float* __restrict__ bnr_g, const float* __restrict__ bnr_b,
                       const float* __restrict__ bnr_m, const float* __restrict__ bnr_v) {
    int idx = blockIdx.x * blockDim.x + threadIdx.x;
    if (idx < COUTC*COUTC*9) {
        int o = idx / (COUTC*9);
        float s2 = bn2_g[o] * rsqrtf(bn2_v[o] + EPSB);
        g_wt2[idx] = wt[idx] * s2;
    }
    if (idx < COUTC*CINC) {
        int o = idx / CINC, c = idx % CINC;
        float s1 = bn1_g[o] * rsqrtf(bn1_v[o] + EPSB);
        float sr = bnr_g[o] * rsqrtf(bnr_v[o] + EPSB);
        g_w3fT[c*COUTC + o] = w3[idx] * s1;
        g_w4fT[c*COUTC + o] = w4[idx] * s1;
        g_wr2T[c*COUTC + o] = wr[idx] * sr;
    }
    if (idx < COUTC) {
        int o = idx;
        float s1 = bn1_g[o] * rsqrtf(bn1_v[o] + EPSB);
        float s2 = bn2_g[o] * rsqrtf(bn2_v[o] + EPSB);
        float sr = bnr_g[o] * rsqrtf(bnr_v[o] + EPSB);
        float h1 = bn1_b[o] - bn1_m[o]*s1;
        float h2 = bn2_b[o] - bn2_m[o]*s2;
        float hr = bnr_b[o] - bnr_m[o]*sr;
        g_b3f[o] = b3[o]*s1;
        g_b4f[o] = b4[o]*s1;
        g_h1[o]  = h1;
        g_Cc[o]  = br[o]*sr + hr + bt[o]*s2 + h2;
    }
}

// ---------------- K1: xbar = mean_t x  (block per (n,c)) ----------------
__global__ void k_xbar(const float* __restrict__ x) {
    int blk = blockIdx.x;                 // n*CINC + c
    __shared__ float sb[32*VV];
    int tid = threadIdx.x;                // 800 threads
    if (tid < 800) {
        int v = tid % VV, tg = tid / VV;  // tg in 0..31
        const float* xp = x + (size_t)blk * TDIM * VV;
        float s = 0.f;
        for (int t = tg; t < TDIM; t += 32) s += xp[t*VV + v];
        sb[tg*VV + v] = s;
    }
    __syncthreads();
    if (tid < VV) {
        float tot = 0.f;
        #pragma unroll
        for (int tg = 0; tg < 32; tg++) tot += sb[tg*VV + tid];
        g_xbar[blk*VV + tid] = tot * (1.f / TDIM);
    }
}

// ---------------- K2: p = softmax_v(-(w2.xbar + b2))  (warp per (n,i)) ----------------
__global__ void k_p(const float* __restrict__ w2, const float* __restrict__ b2) {
    int blk = blockIdx.x;                 // n*ICC + i
    int n = blk / ICC, i = blk % ICC;
    int v = threadIdx.x;                  // 32 lanes
    float val = -1e30f;
    if (v < VV) {
        float acc = b2[i];
        const float* xb = g_xbar + n*CINC*VV;
        #pragma unroll 8
        for (int c = 0; c < CINC; c++) acc += w2[i*CINC + c] * xb[c*VV + v];
        val = -acc;
    }
    float m = val;
    #pragma unroll
    for (int s = 16; s; s >>= 1) m = fmaxf(m, __shfl_xor_sync(0xffffffffu, m, s));
    float e = (v < VV) ? expf(val - m) : 0.f;
    float ssum = e;
    #pragma unroll
    for (int s = 16; s; s >>= 1) ssum += __shfl_xor_sync(0xffffffffu, ssum, s);
    if (v < VV) g_p[blk*VV + v] = e / ssum;
}

// ---------------- K3: spatial/graph mix + BN1/ReLU + residual  (block per (n,t)) ----------------
__global__ void __launch_bounds__(COUTC) k_spatial(const float* __restrict__ x,
                                                   const float* __restrict__ A) {
    int t = blockIdx.x, n = blockIdx.y;
    __shared__ float xs[CINC*VV];   // x[n,:,t,:]
    __shared__ float ps[ICC*VV];    // p[n,:,:]
    __shared__ float As[VV*VV];     // A
    int tid = threadIdx.x;          // 128, thread = output channel o
    for (int idx = tid; idx < CINC*VV; idx += COUTC) {
        int c = idx / VV, v = idx - c*VV;
        xs[idx] = x[(((size_t)n*CINC + c)*TDIM + t)*VV + v];
    }
    for (int idx = tid; idx < ICC*VV; idx += COUTC) ps[idx] = g_p[n*ICC*VV + idx];
    for (int idx = tid; idx < VV*VV; idx += COUTC) As[idx] = A[idx];
    __syncthreads();

    int o = tid;
    float z3[VV], z4[VV], zr[VV];
    #pragma unroll
    for (int v = 0; v < VV; v++) { z3[v] = 0.f; z4[v] = 0.f; zr[v] = 0.f; }

    for (int c = 0; c < CINC; c++) {
        float w3 = g_w3fT[c*COUTC + o];
        float w4 = g_w4fT[c*COUTC + o];
        float wr = g_wr2T[c*COUTC + o];
        const float* xv = &xs[c*VV];
        #pragma unroll
        for (int v = 0; v < VV; v++) {
            float xx = xv[v];
            z3[v] += w3 * xx;
            z4[v] += w4 * xx;
            zr[v] += wr * xx;
        }
    }
    // graph mix collapses: a[n,c,u,v] = p[n,c,v] (softmax of x1[u]-x2[v] is u-independent)
    float q = g_b3f[o];                 // sum_v p = 1 -> bias passes through
    const float* pp = &ps[(o & (ICC-1)) * VV];
    #pragma unroll
    for (int v = 0; v < VV; v++) q += pp[v] * z3[v];

    float b4 = g_b4f[o];
    #pragma unroll
    for (int v = 0; v < VV; v++) z4[v] += b4;

    float base = q + g_h1[o];
    float Cr = g_Cc[o];
    size_t ob = (((size_t)n*COUTC + o)*TDIM + t)*VV;
    #pragma unroll
    for (int u = 0; u < VV; u++) {
        float acc = base;
        const float* Ar = &As[u*VV];
        #pragma unroll
        for (int v = 0; v < VV; v++) acc += Ar[v] * z4[v];
        g_h[ob + u] = fmaxf(acc, 0.f);        // BN1-folded + ReLU
        g_r[ob + u] = zr[u] + Cr;             // residual + all epilogue constants
    }
}

// ---------------- K4: temporal conv (9 taps) + residual + ReLU ----------------
#define OT  16   // output channels per block
#define TTI 16   // t positions per block
#define UP  28   // V padded to 28 for float4 smem rows

__global__ void __launch_bounds__(256) k_temporal(float* __restrict__ out) {
    int t0 = blockIdx.x * TTI;
    int o0 = blockIdx.y * OT;
    int n  = blockIdx.z;
    __shared__ __align__(16) float hs[(TTI + 8) * UP];   // 672 floats
    __shared__ float ws[OT * 9];
    int tid = threadIdx.x;
    int oo  = tid >> 4;       // 0..15
    int ttt = tid & 15;       // 0..15
    int o   = o0 + oo;

    float acc[UP];
    #pragma unroll
    for (int j = 0; j < UP; j++) acc[j] = 0.f;

    for (int i = 0; i < COUTC; i++) {
        const float* hp = g_h + ((size_t)n*COUTC + i) * TDIM * VV;
        #pragma unroll
        for (int idx = tid; idx < (TTI + 8) * UP; idx += 256) {
            int r = idx / UP, u = idx - r*UP;
            int tg = t0 + r - 4;
            float val = 0.f;
            if (u < VV && tg >= 0 && tg < TDIM) val = hp[tg*VV + u];
            hs[idx] = val;
        }
        if (tid < OT*9) {
            int ooo = tid / 9, k = tid - ooo*9;
            ws[tid] = g_wt2[(o0 + ooo)*(COUTC*9) + i*9 + k];
        }
        __syncthreads();

        float w[9];
        #pragma unroll
        for (int k = 0; k < 9; k++) w[k] = ws[oo*9 + k];
        #pragma unroll
        for (int k = 0; k < 9; k++) {
            const float4* hv = (const float4*)&hs[(ttt + k) * UP];
            #pragma unroll
            for (int j = 0; j < 7; j++) {
                float4 h4 = hv[j];
                acc[4*j+0] += w[k] * h4.x;
                acc[4*j+1] += w[k] * h4.y;
                acc[4*j+2] += w[k] * h4.z;
                acc[4*j+3] += w[k] * h4.w;
            }
        }
        __syncthreads();
    }

    size_t ob = (((size_t)n*COUTC + o)*TDIM + (t0 + ttt)) * VV;
    #pragma unroll
    for (int u = 0; u < VV; u++) {
        out[ob + u] = fmaxf(acc[u] + g_r[ob + u], 0.f);
    }
}

// ---------------- launch ----------------
extern "C" void kernel_launch(void* const* d_in, const int* in_sizes, int n_in,
                              void* d_out, int out_size) {
    const float* x     = (const float*)d_in[0];
    const float* A     = (const float*)d_in[1];
    // d_in[2]=w1, d_in[3]=b1: mathematically unused (softmax of x1[u]-x2[v] over v is x1-independent)
    const float* w2    = (const float*)d_in[4];
    const float* b2    = (const float*)d_in[5];
    const float* w3    = (const float*)d_in[6];
    const float* b3    = (const float*)d_in[7];
    const float* w4    = (const float*)d_in[8];
    const float* b4    = (const float*)d_in[9];
    const float* bn1_g = (const float*)d_in[10];
    const float* bn1_b = (const float*)d_in[11];
    const float* bn1_m = (const float*)d_in[12];
    const float* bn1_v = (const float*)d_in[13];
    const float* wt    = (const float*)d_in[14];
    const float* bt    = (const float*)d_in[15];
    const float* bn2_g = (const float*)d_in[16];
    const float* bn2_b = (const float*)d_in[17];
    const float* bn2_m = (const float*)d_in[18];
    const float* bn2_v = (const float*)d_in[19];
    const float* wr    = (const float*)d_in[20];
    const float* br    = (const float*)d_in[21];
    const float* bnr_g = (const float*)d_in[22];
    const float* bnr_b = (const float*)d_in[23];
    const float* bnr_m = (const float*)d_in[24];
    const float* bnr_v = (const float*)d_in[25];
    float* out = (float*)d_out;

    k_fold<<<(COUTC*COUTC*9 + 255)/256, 256>>>(w3, b3, w4, b4,
                                               bn1_g, bn1_b, bn1_m, bn1_v,
                                               wt, bt, bn2_g, bn2_b, bn2_m, bn2_v,
                                               wr, br, bnr_g, bnr_b, bnr_m, bnr_v);
    k_xbar<<<NB*CINC, 800>>>(x);
    k_p<<<NB*ICC, 32>>>(w2, b2);
    k_spatial<<<dim3(TDIM, NB), COUTC>>>(x, A);
    k_temporal<<<dim3(TDIM/TTI, COUTC/OT, NB), 256>>>(out);
}

// round 8
// speedup vs baseline: 2.6389x; 2.6389x over previous
#include <cuda_runtime.h>
#include <cstdint>

#define NB   32
#define CINC 64
#define COUTC 128
#define TDIM 256
#define VV   25
#define ICC  32
#define EPSB 1e-5f

// ---------------- scratch (device globals, no allocation) ----------------
__device__ float g_h[(size_t)NB*COUTC*TDIM*VV];   // BN1+ReLU activations [n][i][t][u]
__device__ float g_r[(size_t)NB*COUTC*TDIM*VV];   // residual branch + epilogue constants [n][o][t][u]
__device__ float g_hT[(size_t)NB*VV*COUTC*TDIM];  // tf32-rounded h, [(n*25+u)*128+i][t]
__device__ float g_y[(size_t)NB*VV*COUTC*TDIM];   // temporal-conv result, [(n*25+u)*128+o][t]
__device__ float g_xbar[NB*CINC*VV];
__device__ float g_p[NB*ICC*VV];
__device__ float g_w3fT[CINC*COUTC];
__device__ float g_w4fT[CINC*COUTC];
__device__ float g_wr2T[CINC*COUTC];
__device__ float g_b3f[COUTC];
__device__ float g_b4f[COUTC];
__device__ float g_h1[COUTC];
__device__ float g_Cc[COUTC];
__device__ float g_wt2[COUTC*COUTC*9];            // wt * s2, tf32-rounded, [o][i][k]

// ---------------- helpers ----------------
__device__ __forceinline__ float to_tf32(float x) {
    uint32_t r;
    asm("cvt.rna.tf32.f32 %0, %1;" : "=r"(r) : "f"(x));
    return __uint_as_float(r);
}

// ---------------- K0: BN folding ----------------
__global__ void k_fold(const float* __restrict__ w3, const float* __restrict__ b3,
                       const float* __restrict__ w4, const float* __restrict__ b4,
                       const float* __restrict__ bn1_g, const float* __restrict__ bn1_b,
                       const float* __restrict__ bn1_m, const float* __restrict__ bn1_v,
                       const float* __restrict__ wt,  const float* __restrict__ bt,
                       const float* __restrict__ bn2_g, const float* __restrict__ bn2_b,
                       const float* __restrict__ bn2_m, const float* __restrict__ bn2_v,
                       const float* __restrict__ wr,  const float* __restrict__ br,
                       const float* __restrict__ bnr_g, const float* __restrict__ bnr_b,
                       const float* __restrict__ bnr_m, const float* __restrict__ bnr_v) {
    int idx = blockIdx.x * blockDim.x + threadIdx.x;
    if (idx < COUTC*COUTC*9) {
        int o = idx / (COUTC*9);
        float s2 = bn2_g[o] * rsqrtf(bn2_v[o] + EPSB);
        g_wt2[idx] = to_tf32(wt[idx] * s2);
    }
    if (idx < COUTC*CINC) {
        int o = idx / CINC, c = idx % CINC;
        float s1 = bn1_g[o] * rsqrtf(bn1_v[o] + EPSB);
        float sr = bnr_g[o] * rsqrtf(bnr_v[o] + EPSB);
        g_w3fT[c*COUTC + o] = w3[idx] * s1;
        g_w4fT[c*COUTC + o] = w4[idx] * s1;
        g_wr2T[c*COUTC + o] = wr[idx] * sr;
    }
    if (idx < COUTC) {
        int o = idx;
        float s1 = bn1_g[o] * rsqrtf(bn1_v[o] + EPSB);
        float s2 = bn2_g[o] * rsqrtf(bn2_v[o] + EPSB);
        float sr = bnr_g[o] * rsqrtf(bnr_v[o] + EPSB);
        float h1 = bn1_b[o] - bn1_m[o]*s1;
        float h2 = bn2_b[o] - bn2_m[o]*s2;
        float hr = bnr_b[o] - bnr_m[o]*sr;
        g_b3f[o] = b3[o]*s1;
        g_b4f[o] = b4[o]*s1;
        g_h1[o]  = h1;
        g_Cc[o]  = br[o]*sr + hr + bt[o]*s2 + h2;
    }
}

// ---------------- K1: xbar = mean_t x ----------------
__global__ void k_xbar(const float* __restrict__ x) {
    int blk = blockIdx.x;
    __shared__ float sb[32*VV];
    int tid = threadIdx.x;
    if (tid < 800) {
        int v = tid % VV, tg = tid / VV;
        const float* xp = x + (size_t)blk * TDIM * VV;
        float s = 0.f;
        for (int t = tg; t < TDIM; t += 32) s += xp[t*VV + v];
        sb[tg*VV + v] = s;
    }
    __syncthreads();
    if (tid < VV) {
        float tot = 0.f;
        #pragma unroll
        for (int tg = 0; tg < 32; tg++) tot += sb[tg*VV + tid];
        g_xbar[blk*VV + tid] = tot * (1.f / TDIM);
    }
}

// ---------------- K2: p = softmax_v(-(w2.xbar + b2)) ----------------
__global__ void k_p(const float* __restrict__ w2, const float* __restrict__ b2) {
    int blk = blockIdx.x;
    int n = blk / ICC, i = blk % ICC;
    int v = threadIdx.x;
    float val = -1e30f;
    if (v < VV) {
        float acc = b2[i];
        const float* xb = g_xbar + n*CINC*VV;
        #pragma unroll 8
        for (int c = 0; c < CINC; c++) acc += w2[i*CINC + c] * xb[c*VV + v];
        val = -acc;
    }
    float m = val;
    #pragma unroll
    for (int s = 16; s; s >>= 1) m = fmaxf(m, __shfl_xor_sync(0xffffffffu, m, s));
    float e = (v < VV) ? expf(val - m) : 0.f;
    float ssum = e;
    #pragma unroll
    for (int s = 16; s; s >>= 1) ssum += __shfl_xor_sync(0xffffffffu, ssum, s);
    if (v < VV) g_p[blk*VV + v] = e / ssum;
}

// ---------------- K3: spatial/graph mix + BN1/ReLU + residual ----------------
__global__ void __launch_bounds__(COUTC) k_spatial(const float* __restrict__ x,
                                                   const float* __restrict__ A) {
    int t = blockIdx.x, n = blockIdx.y;
    __shared__ float xs[CINC*VV];
    __shared__ float ps[ICC*VV];
    __shared__ float As[VV*VV];
    int tid = threadIdx.x;
    for (int idx = tid; idx < CINC*VV; idx += COUTC) {
        int c = idx / VV, v = idx - c*VV;
        xs[idx] = x[(((size_t)n*CINC + c)*TDIM + t)*VV + v];
    }
    for (int idx = tid; idx < ICC*VV; idx += COUTC) ps[idx] = g_p[n*ICC*VV + idx];
    for (int idx = tid; idx < VV*VV; idx += COUTC) As[idx] = A[idx];
    __syncthreads();

    int o = tid;
    float z3[VV], z4[VV], zr[VV];
    #pragma unroll
    for (int v = 0; v < VV; v++) { z3[v] = 0.f; z4[v] = 0.f; zr[v] = 0.f; }

    for (int c = 0; c < CINC; c++) {
        float w3 = g_w3fT[c*COUTC + o];
        float w4 = g_w4fT[c*COUTC + o];
        float wr = g_wr2T[c*COUTC + o];
        const float* xv = &xs[c*VV];
        #pragma unroll
        for (int v = 0; v < VV; v++) {
            float xx = xv[v];
            z3[v] += w3 * xx;
            z4[v] += w4 * xx;
            zr[v] += wr * xx;
        }
    }
    float q = g_b3f[o];
    const float* pp = &ps[(o & (ICC-1)) * VV];
    #pragma unroll
    for (int v = 0; v < VV; v++) q += pp[v] * z3[v];

    float b4 = g_b4f[o];
    #pragma unroll
    for (int v = 0; v < VV; v++) z4[v] += b4;

    float base = q + g_h1[o];
    float Cr = g_Cc[o];
    size_t ob = (((size_t)n*COUTC + o)*TDIM + t)*VV;
    #pragma unroll
    for (int u = 0; u < VV; u++) {
        float acc = base;
        const float* Ar = &As[u*VV];
        #pragma unroll
        for (int v = 0; v < VV; v++) acc += Ar[v] * z4[v];
        g_h[ob + u] = fmaxf(acc, 0.f);
        g_r[ob + u] = zr[u] + Cr;
    }
}

// ---------------- K3.5: transpose g_h [n][i][t][u] -> g_hT [(n,u,i)][t], tf32-rounded --------
__global__ void __launch_bounds__(256) k_tr() {
    int blk = blockIdx.x;                 // n*128 + i
    int n = blk >> 7, i = blk & 127;
    __shared__ float s[VV * 257];
    const float* src = g_h + (size_t)blk * (TDIM*VV);
    int tid = threadIdx.x;
    for (int idx = tid; idx < TDIM*VV; idx += 256) {
        int t = idx / VV, u = idx - VV*t;
        s[u*257 + t] = src[idx];
    }
    __syncthreads();
    float* dst = g_hT + (((size_t)n*VV)*COUTC + i)*TDIM;
    #pragma unroll
    for (int u = 0; u < VV; u++) {
        dst[(size_t)u*COUTC*TDIM + tid] = to_tf32(s[u*257 + tid]);
    }
}

// ---------------- K4: temporal conv as warp-level tf32 mma.sync GEMM ----------------
// Per block (n, u, th): D[o=128, t=128] = sum_{kk=0..1151} Wt2[o,kk] * H[kk,t]
//   kk = i*9+k,  H[kk,t] = hT[(n,u,i)][t0+t+k-4] (0 outside [0,256))
// 8 warps: warp_m = wid&3 (32 o-rows), warp_n = wid>>2 (64 t-cols). Warp tile 32x64.
// mma.sync.aligned.m16n8k8.row.col.f32.tf32.tf32.f32
#define NCHUNK 36      // 36 chunks x 32 kk = 1152
#define PA 36          // sA pitch: A-frag read banks (4g+tg)%32 all distinct
#define PB 136         // sB pitch: B-frag read banks (8tg+g)%32 all distinct

__global__ void __launch_bounds__(256) k_mma() {
    __shared__ float smem_all[COUTC*PA + 32*PB];   // 4608 + 4352 = 8960 floats (35.8KB)
    float* sA = smem_all;                          // [o][k] 128 x 36
    float* sB = smem_all + COUTC*PA;               // [k][t] 32 x 136

    int tid = threadIdx.x, wid = tid >> 5, lane = tid & 31;
    int g = lane >> 2, tg = lane & 3;
    int warp_m = wid & 3, warp_n = wid >> 2;
    int t0 = blockIdx.x * 128;
    int u  = blockIdx.y;
    int n  = blockIdx.z;

    const float* hrow = g_hT + (((size_t)n*VV + u)*COUTC)*TDIM;

    float acc[2][8][4];
    #pragma unroll
    for (int mt = 0; mt < 2; mt++)
        #pragma unroll
        for (int nt = 0; nt < 8; nt++)
            #pragma unroll
            for (int q = 0; q < 4; q++) acc[mt][nt][q] = 0.f;

    for (int c = 0; c < NCHUNK; c++) {
        __syncthreads();   // previous chunk's LDS (or epilogue alias) done before refill
        // fill sA[o][j]: coalesced along j
        #pragma unroll
        for (int e = 0; e < 16; e++) {
            int idx = e*256 + tid;
            int o = idx >> 5, j = idx & 31;
            sA[o*PA + j] = g_wt2[o*1152 + c*32 + j];
        }
        // fill sB[j][t]: coalesced along t (gmem contiguous), conflict-free STS
        #pragma unroll
        for (int e = 0; e < 16; e++) {
            int idx = e*256 + tid;
            int j = idx >> 7, t = idx & 127;
            int kk = c*32 + j;
            int i = kk / 9;
            int k = kk - i*9;
            int tgidx = t0 + t + k - 4;
            float v = 0.f;
            if (tgidx >= 0 && tgidx < TDIM) v = hrow[(size_t)i*TDIM + tgidx];
            sB[j*PB + t] = v;
        }
        __syncthreads();

        #pragma unroll
        for (int ks = 0; ks < 4; ks++) {
            int k0 = ks*8;
            uint32_t a[2][4];
            #pragma unroll
            for (int mt = 0; mt < 2; mt++) {
                int ob = warp_m*32 + mt*16;
                a[mt][0] = __float_as_uint(sA[(ob + g    )*PA + k0 + tg    ]);
                a[mt][1] = __float_as_uint(sA[(ob + g + 8)*PA + k0 + tg    ]);
                a[mt][2] = __float_as_uint(sA[(ob + g    )*PA + k0 + tg + 4]);
                a[mt][3] = __float_as_uint(sA[(ob + g + 8)*PA + k0 + tg + 4]);
            }
            #pragma unroll
            for (int nt = 0; nt < 8; nt++) {
                int tb = warp_n*64 + nt*8;
                uint32_t b0 = __float_as_uint(sB[(k0 + tg    )*PB + tb + g]);
                uint32_t b1 = __float_as_uint(sB[(k0 + tg + 4)*PB + tb + g]);
                #pragma unroll
                for (int mt = 0; mt < 2; mt++) {
                    asm volatile(
                        "mma.sync.aligned.m16n8k8.row.col.f32.tf32.tf32.f32 "
                        "{%0,%1,%2,%3}, {%4,%5,%6,%7}, {%8,%9}, {%0,%1,%2,%3};"
                        : "+f"(acc[mt][nt][0]), "+f"(acc[mt][nt][1]),
                          "+f"(acc[mt][nt][2]), "+f"(acc[mt][nt][3])
                        : "r"(a[mt][0]), "r"(a[mt][1]), "r"(a[mt][2]), "r"(a[mt][3]),
                          "r"(b0), "r"(b1));
                }
            }
        }
    }

    // Epilogue: accumulators -> smem stage (one 64-t half at a time) -> g_y (t-contiguous)
    float* stage = smem_all;   // 128 x 68 = 8704 floats, aliases sA/sB
    size_t yb = (((size_t)n*VV + u)*COUTC)*TDIM + t0;
    #pragma unroll
    for (int rr = 0; rr < 2; rr++) {
        __syncthreads();       // mainloop LDS / previous copy done before overwrite
        if (warp_n == rr) {
            #pragma unroll
            for (int mt = 0; mt < 2; mt++) {
                int o = warp_m*32 + mt*16 + g;
                #pragma unroll
                for (int nt = 0; nt < 8; nt++) {
                    int tl = nt*8 + 2*tg;
                    stage[ o     *68 + tl    ] = acc[mt][nt][0];
                    stage[ o     *68 + tl + 1] = acc[mt][nt][1];
                    stage[(o + 8)*68 + tl    ] = acc[mt][nt][2];
                    stage[(o + 8)*68 + tl + 1] = acc[mt][nt][3];
                }
            }
        }
        __syncthreads();
        #pragma unroll
        for (int e = 0; e < 32; e++) {
            int idx = e*256 + tid;            // 128*64
            int o = idx >> 6, tl = idx & 63;
            g_y[yb + (size_t)o*TDIM + rr*64 + tl] = stage[o*68 + tl];
        }
    }
}

// ---------------- K5: y + residual + ReLU, back to [n][o][t][u] ----------------
__global__ void __launch_bounds__(256) k_out(float* __restrict__ out) {
    int blk = blockIdx.x;                  // n*128 + o
    int n = blk >> 7, o = blk & 127;
    __shared__ float sy[TDIM * 27];
    int tid = threadIdx.x;
    size_t ybase = (((size_t)n*VV)*COUTC + o)*TDIM;   // + u*COUTC*TDIM
    #pragma unroll
    for (int u = 0; u < VV; u++) {
        sy[tid*27 + u] = g_y[ybase + (size_t)u*COUTC*TDIM + tid];
    }
    __syncthreads();
    size_t ob = ((size_t)n*COUTC + o) * TDIM * VV;
    for (int idx = tid; idx < TDIM*VV; idx += 256) {
        int t = idx / VV, u = idx - VV*t;
        out[ob + idx] = fmaxf(sy[t*27 + u] + g_r[ob + idx], 0.f);
    }
}

// ---------------- launch ----------------
extern "C" void kernel_launch(void* const* d_in, const int* in_sizes, int n_in,
                              void* d_out, int out_size) {
    const float* x     = (const float*)d_in[0];
    const float* A     = (const float*)d_in[1];
    const float* w2    = (const float*)d_in[4];
    const float* b2    = (const float*)d_in[5];
    const float* w3    = (const float*)d_in[6];
    const float* b3    = (const float*)d_in[7];
    const float* w4    = (const float*)d_in[8];
    const float* b4    = (const float*)d_in[9];
    const float* bn1_g = (const float*)d_in[10];
    const float* bn1_b = (const float*)d_in[11];
    const float* bn1_m = (const float*)d_in[12];
    const float* bn1_v = (const float*)d_in[13];
    const float* wt    = (const float*)d_in[14];
    const float* bt    = (const float*)d_in[15];
    const float* bn2_g = (const float*)d_in[16];
    const float* bn2_b = (const float*)d_in[17];
    const float* bn2_m = (const float*)d_in[18];
    const float* bn2_v = (const float*)d_in[19];
    const float* wr    = (const float*)d_in[20];
    const float* br    = (const float*)d_in[21];
    const float* bnr_g = (const float*)d_in[22];
    const float* bnr_b = (const float*)d_in[23];
    const float* bnr_m = (const float*)d_in[24];
    const float* bnr_v = (const float*)d_in[25];
    float* out = (float*)d_out;

    k_fold<<<(COUTC*COUTC*9 + 255)/256, 256>>>(w3, b3, w4, b4,
                                               bn1_g, bn1_b, bn1_m, bn1_v,
                                               wt, bt, bn2_g, bn2_b, bn2_m, bn2_v,
                                               wr, br, bnr_g, bnr_b, bnr_m, bnr_v);
    k_xbar<<<NB*CINC, 800>>>(x);
    k_p<<<NB*ICC, 32>>>(w2, b2);
    k_spatial<<<dim3(TDIM, NB), COUTC>>>(x, A);
    k_tr<<<NB*COUTC, 256>>>();
    k_mma<<<dim3(2, VV, NB), 256>>>();
    k_out<<<NB*COUTC, 256>>>(out);
}

// round 9
// speedup vs baseline: 2.9129x; 1.1038x over previous
#include <cuda_runtime.h>
#include <cstdint>

#define NB   32
#define CINC 64
#define COUTC 128
#define TDIM 256
#define VV   25
#define ICC  32
#define EPSB 1e-5f

// ---------------- scratch (device globals, no allocation) ----------------
__device__ float g_h[(size_t)NB*COUTC*TDIM*VV];   // BN1+ReLU activations [n][i][t][u]
__device__ float g_r[(size_t)NB*COUTC*TDIM*VV];   // residual branch + epilogue constants [n][o][t][u]
__device__ float g_hT[(size_t)NB*VV*COUTC*TDIM];  // tf32-rounded h, [(n*25+u)*128+i][t]
__device__ float g_y[(size_t)NB*VV*COUTC*TDIM];   // temporal-conv result, [(n*25+u)*128+o][t]
__device__ float g_xbar[NB*CINC*VV];
__device__ float g_p[NB*ICC*VV];
__device__ float g_w3fT[CINC*COUTC];
__device__ float g_w4fT[CINC*COUTC];
__device__ float g_wr2T[CINC*COUTC];
__device__ float g_b3f[COUTC];
__device__ float g_b4f[COUTC];
__device__ float g_h1[COUTC];
__device__ float g_Cc[COUTC];
__device__ float g_wt2[COUTC*COUTC*9];            // wt * s2, tf32-rounded, [o][i][k]

// ---------------- helpers ----------------
__device__ __forceinline__ float to_tf32(float x) {
    uint32_t r;
    asm("cvt.rna.tf32.f32 %0, %1;" : "=r"(r) : "f"(x));
    return __uint_as_float(r);
}
__device__ __forceinline__ uint32_t smem_u32(const void* p) {
    uint32_t a;
    asm("{ .reg .u64 t; cvta.to.shared.u64 t, %1; cvt.u32.u64 %0, t; }" : "=r"(a) : "l"(p));
    return a;
}

// ---------------- K0: BN folding ----------------
__global__ void k_fold(const float* __restrict__ w3, const float* __restrict__ b3,
                       const float* __restrict__ w4, const float* __restrict__ b4,
                       const float* __restrict__ bn1_g, const float* __restrict__ bn1_b,
                       const float* __restrict__ bn1_m, const float* __restrict__ bn1_v,
                       const float* __restrict__ wt,  const float* __restrict__ bt,
                       const float* __restrict__ bn2_g, const float* __restrict__ bn2_b,
                       const float* __restrict__ bn2_m, const float* __restrict__ bn2_v,
                       const float* __restrict__ wr,  const float* __restrict__ br,
                       const float* __restrict__ bnr_g, const float* __restrict__ bnr_b,
                       const float* __restrict__ bnr_m, const float* __restrict__ bnr_v) {
    int idx = blockIdx.x * blockDim.x + threadIdx.x;
    if (idx < COUTC*COUTC*9) {
        int o = idx / (COUTC*9);
        float s2 = bn2_g[o] * rsqrtf(bn2_v[o] + EPSB);
        g_wt2[idx] = to_tf32(wt[idx] * s2);
    }
    if (idx < COUTC*CINC) {
        int o = idx / CINC, c = idx % CINC;
        float s1 = bn1_g[o] * rsqrtf(bn1_v[o] + EPSB);
        float sr = bnr_g[o] * rsqrtf(bnr_v[o] + EPSB);
        g_w3fT[c*COUTC + o] = w3[idx] * s1;
        g_w4fT[c*COUTC + o] = w4[idx] * s1;
        g_wr2T[c*COUTC + o] = wr[idx] * sr;
    }
    if (idx < COUTC) {
        int o = idx;
        float s1 = bn1_g[o] * rsqrtf(bn1_v[o] + EPSB);
        float s2 = bn2_g[o] * rsqrtf(bn2_v[o] + EPSB);
        float sr = bnr_g[o] * rsqrtf(bnr_v[o] + EPSB);
        float h1 = bn1_b[o] - bn1_m[o]*s1;
        float h2 = bn2_b[o] - bn2_m[o]*s2;
        float hr = bnr_b[o] - bnr_m[o]*sr;
        g_b3f[o] = b3[o]*s1;
        g_b4f[o] = b4[o]*s1;
        g_h1[o]  = h1;
        g_Cc[o]  = br[o]*sr + hr + bt[o]*s2 + h2;
    }
}

// ---------------- K1: xbar = mean_t x ----------------
__global__ void k_xbar(const float* __restrict__ x) {
    int blk = blockIdx.x;
    __shared__ float sb[32*VV];
    int tid = threadIdx.x;
    if (tid < 800) {
        int v = tid % VV, tg = tid / VV;
        const float* xp = x + (size_t)blk * TDIM * VV;
        float s = 0.f;
        for (int t = tg; t < TDIM; t += 32) s += xp[t*VV + v];
        sb[tg*VV + v] = s;
    }
    __syncthreads();
    if (tid < VV) {
        float tot = 0.f;
        #pragma unroll
        for (int tg = 0; tg < 32; tg++) tot += sb[tg*VV + tid];
        g_xbar[blk*VV + tid] = tot * (1.f / TDIM);
    }
}

// ---------------- K2: p = softmax_v(-(w2.xbar + b2)) ----------------
__global__ void k_p(const float* __restrict__ w2, const float* __restrict__ b2) {
    int blk = blockIdx.x;
    int n = blk / ICC, i = blk % ICC;
    int v = threadIdx.x;
    float val = -1e30f;
    if (v < VV) {
        float acc = b2[i];
        const float* xb = g_xbar + n*CINC*VV;
        #pragma unroll 8
        for (int c = 0; c < CINC; c++) acc += w2[i*CINC + c] * xb[c*VV + v];
        val = -acc;
    }
    float m = val;
    #pragma unroll
    for (int s = 16; s; s >>= 1) m = fmaxf(m, __shfl_xor_sync(0xffffffffu, m, s));
    float e = (v < VV) ? expf(val - m) : 0.f;
    float ssum = e;
    #pragma unroll
    for (int s = 16; s; s >>= 1) ssum += __shfl_xor_sync(0xffffffffu, ssum, s);
    if (v < VV) g_p[blk*VV + v] = e / ssum;
}

// ---------------- K3: spatial/graph mix + BN1/ReLU + residual (512 thr, v-split) ----------
__global__ void __launch_bounds__(512, 2) k_spatial(const float* __restrict__ x,
                                                    const float* __restrict__ A) {
    int t = blockIdx.x, n = blockIdx.y;
    __shared__ float xs[CINC*VV];      // 1600
    __shared__ float ps[ICC*VV];       // 800
    __shared__ float As[VV*VV];        // 625
    __shared__ float z4s[COUTC*26];    // 3328, pitch 26 (conflict-free)
    __shared__ float qs[4*COUTC];      // 512
    int tid = threadIdx.x;
    int o = tid & 127, vh = tid >> 7;            // 4 v-groups
    const int vst[4] = {0, 7, 13, 19};
    const int vcn[4] = {7, 6, 6, 6};
    int v0 = vst[vh], vc = vcn[vh];

    for (int idx = tid; idx < CINC*VV; idx += 512) {
        int c = idx / VV, v = idx - c*VV;
        xs[idx] = x[(((size_t)n*CINC + c)*TDIM + t)*VV + v];
    }
    for (int idx = tid; idx < ICC*VV; idx += 512) ps[idx] = g_p[n*ICC*VV + idx];
    for (int idx = tid; idx < VV*VV; idx += 512) As[idx] = A[idx];
    __syncthreads();

    float z3[7], z4[7], zr[7];
    #pragma unroll
    for (int j = 0; j < 7; j++) { z3[j] = 0.f; z4[j] = 0.f; zr[j] = 0.f; }

    for (int c = 0; c < CINC; c++) {
        float w3 = g_w3fT[c*COUTC + o];
        float w4 = g_w4fT[c*COUTC + o];
        float wr = g_wr2T[c*COUTC + o];
        const float* xv = &xs[c*VV + v0];
        #pragma unroll
        for (int j = 0; j < 7; j++) {
            if (j < vc) {
                float xx = xv[j];
                z3[j] += w3 * xx;
                z4[j] += w4 * xx;
                zr[j] += wr * xx;
            }
        }
    }

    float b4 = g_b4f[o];
    float qp = 0.f;
    const float* pp = &ps[(o & (ICC-1)) * VV + v0];
    #pragma unroll
    for (int j = 0; j < 7; j++) if (j < vc) qp += pp[j] * z3[j];
    qs[vh*COUTC + o] = qp;
    #pragma unroll
    for (int j = 0; j < 7; j++) if (j < vc) z4s[o*26 + v0 + j] = z4[j] + b4;
    __syncthreads();

    float base = qs[o] + qs[COUTC + o] + qs[2*COUTC + o] + qs[3*COUTC + o]
               + g_b3f[o] + g_h1[o];
    float Cr = g_Cc[o];
    size_t ob = (((size_t)n*COUTC + o)*TDIM + t)*VV;
    #pragma unroll
    for (int j = 0; j < 7; j++) {
        if (j < vc) {
            int u = v0 + j;
            float acc = base;
            const float* Ar = &As[u*VV];
            #pragma unroll
            for (int v = 0; v < VV; v++) acc += Ar[v] * z4s[o*26 + v];
            g_h[ob + u] = fmaxf(acc, 0.f);
            g_r[ob + u] = zr[j] + Cr;
        }
    }
}

// ---------------- K3.5: transpose g_h [n][i][t][u] -> g_hT [(n,u,i)][t], tf32-rounded --------
__global__ void __launch_bounds__(256) k_tr() {
    int blk = blockIdx.x;                 // n*128 + i
    int n = blk >> 7, i = blk & 127;
    __shared__ float s[VV * 257];
    const float* src = g_h + (size_t)blk * (TDIM*VV);
    int tid = threadIdx.x;
    for (int idx = tid; idx < TDIM*VV; idx += 256) {
        int t = idx / VV, u = idx - VV*t;
        s[u*257 + t] = src[idx];
    }
    __syncthreads();
    float* dst = g_hT + (((size_t)n*VV)*COUTC + i)*TDIM;
    #pragma unroll
    for (int u = 0; u < VV; u++) {
        dst[(size_t)u*COUTC*TDIM + tid] = to_tf32(s[u*257 + tid]);
    }
}

// ---------------- K4: temporal conv as warp-level tf32 mma.sync GEMM ----------------
// D[o=128, t=128] per (n, u, th); K=1152 in 72 chunks of 16, double-buffered cp.async.
#define NCHUNK 72
#define KC 16          // k per chunk
#define PA 20          // sA pitch: A-frag banks (4g+tg)%32 distinct (20%32 ≡ 4 mod 8 pattern ok)
#define PB 136         // sB pitch: B-frag banks (8tg+g)%32 distinct
// float-index offsets inside shared buffer
#define A0_OFF 0
#define A1_OFF 2560
#define B0_OFF 5120
#define B1_OFF 7296
#define SMEM_FL 9472   // 37.9 KB

__global__ void __launch_bounds__(256, 2) k_mma() {
    __shared__ float smem_all[SMEM_FL];
    int tid = threadIdx.x, wid = tid >> 5, lane = tid & 31;
    int g = lane >> 2, tg = lane & 3;
    int warp_m = wid & 3, warp_n = wid >> 2;
    int t0 = blockIdx.x * 128;
    int u  = blockIdx.y;
    int n  = blockIdx.z;

    uint32_t sbase = smem_u32(smem_all);
    const float* hrow = g_hT + (((size_t)n*VV + u)*COUTC)*TDIM;

    float acc[2][8][4];
    #pragma unroll
    for (int mt = 0; mt < 2; mt++)
        #pragma unroll
        for (int nt = 0; nt < 8; nt++)
            #pragma unroll
            for (int q = 0; q < 4; q++) acc[mt][nt][q] = 0.f;

    // ---- async fill of chunk c into buffer buf ----
    auto fill = [&](int c, int buf) {
        uint32_t sa = sbase + (buf ? A1_OFF : A0_OFF) * 4;
        #pragma unroll
        for (int e = 0; e < 8; e++) {
            int idx = e*256 + tid;
            int o = idx >> 4, j = idx & 15;
            uint32_t dst = sa + (o*PA + j)*4;
            const float* src = g_wt2 + o*1152 + c*KC + j;
            asm volatile("cp.async.ca.shared.global [%0], [%1], 4;" :: "r"(dst), "l"(src));
        }
        uint32_t sb = sbase + (buf ? B1_OFF : B0_OFF) * 4;
        #pragma unroll
        for (int e = 0; e < 8; e++) {
            int idx = e*256 + tid;
            int j = idx >> 7, t = idx & 127;
            int kk = c*KC + j;
            int i = kk / 9, k = kk - i*9;
            int tgi = t0 + t + k - 4;
            int inr = (tgi >= 0 && tgi < TDIM) ? 4 : 0;
            int tcl = min(max(tgi, 0), TDIM - 1);
            const float* src = hrow + (size_t)i*TDIM + tcl;
            uint32_t dst = sb + (j*PB + t)*4;
            asm volatile("cp.async.ca.shared.global [%0], [%1], 4, %2;"
                         :: "r"(dst), "l"(src), "r"(inr));
        }
        asm volatile("cp.async.commit_group;" ::: "memory");
    };

    fill(0, 0);
    for (int c = 0; c < NCHUNK; c++) {
        asm volatile("cp.async.wait_group 0;" ::: "memory");
        __syncthreads();                       // fill c visible + prev compute done
        if (c + 1 < NCHUNK) fill(c + 1, (c + 1) & 1);

        const float* sA = smem_all + ((c & 1) ? A1_OFF : A0_OFF);
        const float* sB = smem_all + ((c & 1) ? B1_OFF : B0_OFF);
        #pragma unroll
        for (int ks = 0; ks < 2; ks++) {
            int k0 = ks*8;
            uint32_t a[2][4];
            #pragma unroll
            for (int mt = 0; mt < 2; mt++) {
                int ob = warp_m*32 + mt*16;
                a[mt][0] = __float_as_uint(sA[(ob + g    )*PA + k0 + tg    ]);
                a[mt][1] = __float_as_uint(sA[(ob + g + 8)*PA + k0 + tg    ]);
                a[mt][2] = __float_as_uint(sA[(ob + g    )*PA + k0 + tg + 4]);
                a[mt][3] = __float_as_uint(sA[(ob + g + 8)*PA + k0 + tg + 4]);
            }
            #pragma unroll
            for (int nt = 0; nt < 8; nt++) {
                int tb = warp_n*64 + nt*8;
                uint32_t b0 = __float_as_uint(sB[(k0 + tg    )*PB + tb + g]);
                uint32_t b1 = __float_as_uint(sB[(k0 + tg + 4)*PB + tb + g]);
                #pragma unroll
                for (int mt = 0; mt < 2; mt++) {
                    asm volatile(
                        "mma.sync.aligned.m16n8k8.row.col.f32.tf32.tf32.f32 "
                        "{%0,%1,%2,%3}, {%4,%5,%6,%7}, {%8,%9}, {%0,%1,%2,%3};"
                        : "+f"(acc[mt][nt][0]), "+f"(acc[mt][nt][1]),
                          "+f"(acc[mt][nt][2]), "+f"(acc[mt][nt][3])
                        : "r"(a[mt][0]), "r"(a[mt][1]), "r"(a[mt][2]), "r"(a[mt][3]),
                          "r"(b0), "r"(b1));
                }
            }
        }
    }

    // Epilogue: accumulators -> smem stage (64-t half at a time) -> g_y (t-contiguous)
    float* stage = smem_all;   // 128 x 68 = 8704 <= 9472, aliases buffers
    size_t yb = (((size_t)n*VV + u)*COUTC)*TDIM + t0;
    #pragma unroll
    for (int rr = 0; rr < 2; rr++) {
        __syncthreads();
        if (warp_n == rr) {
            #pragma unroll
            for (int mt = 0; mt < 2; mt++) {
                int o = warp_m*32 + mt*16 + g;
                #pragma unroll
                for (int nt = 0; nt < 8; nt++) {
                    int tl = nt*8 + 2*tg;
                    stage[ o     *68 + tl    ] = acc[mt][nt][0];
                    stage[ o     *68 + tl + 1] = acc[mt][nt][1];
                    stage[(o + 8)*68 + tl    ] = acc[mt][nt][2];
                    stage[(o + 8)*68 + tl + 1] = acc[mt][nt][3];
                }
            }
        }
        __syncthreads();
        #pragma unroll
        for (int e = 0; e < 32; e++) {
            int idx = e*256 + tid;            // 128*64
            int o = idx >> 6, tl = idx & 63;
            g_y[yb + (size_t)o*TDIM + rr*64 + tl] = stage[o*68 + tl];
        }
    }
}

// ---------------- K5: y + residual + ReLU, back to [n][o][t][u] ----------------
__global__ void __launch_bounds__(256) k_out(float* __restrict__ out) {
    int blk = blockIdx.x;                  // n*128 + o
    int n = blk >> 7, o = blk & 127;
    __shared__ float sy[TDIM * 27];
    int tid = threadIdx.x;
    size_t ybase = (((size_t)n*VV)*COUTC + o)*TDIM;
    #pragma unroll
    for (int u = 0; u < VV; u++) {
        sy[tid*27 + u] = g_y[ybase + (size_t)u*COUTC*TDIM + tid];
    }
    __syncthreads();
    size_t ob = ((size_t)n*COUTC + o) * TDIM * VV;
    for (int idx = tid; idx < TDIM*VV; idx += 256) {
        int t = idx / VV, u = idx - VV*t;
        out[ob + idx] = fmaxf(sy[t*27 + u] + g_r[ob + idx], 0.f);
    }
}

// ---------------- launch ----------------
extern "C" void kernel_launch(void* const* d_in, const int* in_sizes, int n_in,
                              void* d_out, int out_size) {
    const float* x     = (const float*)d_in[0];
    const float* A     = (const float*)d_in[1];
    const float* w2    = (const float*)d_in[4];
    const float* b2    = (const float*)d_in[5];
    const float* w3    = (const float*)d_in[6];
    const float* b3    = (const float*)d_in[7];
    const float* w4    = (const float*)d_in[8];
    const float* b4    = (const float*)d_in[9];
    const float* bn1_g = (const float*)d_in[10];
    const float* bn1_b = (const float*)d_in[11];
    const float* bn1_m = (const float*)d_in[12];
    const float* bn1_v = (const float*)d_in[13];
    const float* wt    = (const float*)d_in[14];
    const float* bt    = (const float*)d_in[15];
    const float* bn2_g = (const float*)d_in[16];
    const float* bn2_b = (const float*)d_in[17];
    const float* bn2_m = (const float*)d_in[18];
    const float* bn2_v = (const float*)d_in[19];
    const float* wr    = (const float*)d_in[20];
    const float* br    = (const float*)d_in[21];
    const float* bnr_g = (const float*)d_in[22];
    const float* bnr_b = (const float*)d_in[23];
    const float* bnr_m = (const float*)d_in[24];
    const float* bnr_v = (const float*)d_in[25];
    float* out = (float*)d_out;

    k_fold<<<(COUTC*COUTC*9 + 255)/256, 256>>>(w3, b3, w4, b4,
                                               bn1_g, bn1_b, bn1_m, bn1_v,
                                               wt, bt, bn2_g, bn2_b, bn2_m, bn2_v,
                                               wr, br, bnr_g, bnr_b, bnr_m, bnr_v);
    k_xbar<<<NB*CINC, 800>>>(x);
    k_p<<<NB*ICC, 32>>>(w2, b2);
    k_spatial<<<dim3(TDIM, NB), 512>>>(x, A);
    k_tr<<<NB*COUTC, 256>>>();
    k_mma<<<dim3(2, VV, NB), 256>>>();
    k_out<<<NB*COUTC, 256>>>(out);
}

// round 10
// speedup vs baseline: 4.2539x; 1.4604x over previous
#include <cuda_runtime.h>
#include <cstdint>

#define NB   32
#define CINC 64
#define COUTC 128
#define TDIM 256
#define VV   25
#define ICC  32
#define EPSB 1e-5f
#define JDIM (TDIM*VV)       // 6400 columns (t,v)

// ---------------- scratch (device globals, no allocation) ----------------
__device__ float g_z[(size_t)NB*384*JDIM];        // z3/z4/zr stacked: [n][o'=384][j]
__device__ float g_hT[(size_t)NB*VV*COUTC*TDIM];  // tf32 h, [((n*25+u)*128+i)][t]
__device__ float g_rT[(size_t)NB*VV*COUTC*TDIM];  // residual, same layout as g_hT
__device__ float g_y[(size_t)NB*VV*COUTC*TDIM];   // final (y+r, relu'd), [((n*25+u)*128+o)][t]
__device__ float g_xbar[NB*CINC*VV];
__device__ float g_p[NB*ICC*VV];
__device__ float g_wstk[384*CINC];                // [w3*s1; w4*s1; wr*sr], tf32-rounded
__device__ float g_b3f[COUTC];
__device__ float g_b4f[COUTC];
__device__ float g_h1[COUTC];
__device__ float g_Cc[COUTC];
__device__ float g_wt2[COUTC*COUTC*9];            // wt * s2, tf32-rounded, [o][i][k]

// ---------------- helpers ----------------
__device__ __forceinline__ float to_tf32(float x) {
    uint32_t r;
    asm("cvt.rna.tf32.f32 %0, %1;" : "=r"(r) : "f"(x));
    return __uint_as_float(r);
}
__device__ __forceinline__ uint32_t smem_u32(const void* p) {
    uint32_t a;
    asm("{ .reg .u64 t; cvta.to.shared.u64 t, %1; cvt.u32.u64 %0, t; }" : "=r"(a) : "l"(p));
    return a;
}

// ---------------- K0: BN folding + weight stack ----------------
__global__ void k_fold(const float* __restrict__ w3, const float* __restrict__ b3,
                       const float* __restrict__ w4, const float* __restrict__ b4,
                       const float* __restrict__ bn1_g, const float* __restrict__ bn1_b,
                       const float* __restrict__ bn1_m, const float* __restrict__ bn1_v,
                       const float* __restrict__ wt,  const float* __restrict__ bt,
                       const float* __restrict__ bn2_g, const float* __restrict__ bn2_b,
                       const float* __restrict__ bn2_m, const float* __restrict__ bn2_v,
                       const float* __restrict__ wr,  const float* __restrict__ br,
                       const float* __restrict__ bnr_g, const float* __restrict__ bnr_b,
                       const float* __restrict__ bnr_m, const float* __restrict__ bnr_v) {
    int idx = blockIdx.x * blockDim.x + threadIdx.x;
    if (idx < COUTC*COUTC*9) {
        int o = idx / (COUTC*9);
        float s2 = bn2_g[o] * rsqrtf(bn2_v[o] + EPSB);
        g_wt2[idx] = to_tf32(wt[idx] * s2);
    }
    if (idx < 384*CINC) {
        int op = idx >> 6, c = idx & 63;
        float w, s;
        if (op < 128) {
            s = bn1_g[op] * rsqrtf(bn1_v[op] + EPSB);
            w = w3[op*CINC + c];
        } else if (op < 256) {
            int o = op - 128;
            s = bn1_g[o] * rsqrtf(bn1_v[o] + EPSB);
            w = w4[o*CINC + c];
        } else {
            int o = op - 256;
            s = bnr_g[o] * rsqrtf(bnr_v[o] + EPSB);
            w = wr[o*CINC + c];
        }
        g_wstk[idx] = to_tf32(w * s);
    }
    if (idx < COUTC) {
        int o = idx;
        float s1 = bn1_g[o] * rsqrtf(bn1_v[o] + EPSB);
        float s2 = bn2_g[o] * rsqrtf(bn2_v[o] + EPSB);
        float sr = bnr_g[o] * rsqrtf(bnr_v[o] + EPSB);
        float h1 = bn1_b[o] - bn1_m[o]*s1;
        float h2 = bn2_b[o] - bn2_m[o]*s2;
        float hr = bnr_b[o] - bnr_m[o]*sr;
        g_b3f[o] = b3[o]*s1;
        g_b4f[o] = b4[o]*s1;
        g_h1[o]  = h1;
        g_Cc[o]  = br[o]*sr + hr + bt[o]*s2 + h2;
    }
}

// ---------------- K1: xbar = mean_t x ----------------
__global__ void k_xbar(const float* __restrict__ x) {
    int blk = blockIdx.x;
    __shared__ float sb[32*VV];
    int tid = threadIdx.x;
    if (tid < 800) {
        int v = tid % VV, tg = tid / VV;
        const float* xp = x + (size_t)blk * TDIM * VV;
        float s = 0.f;
        for (int t = tg; t < TDIM; t += 32) s += xp[t*VV + v];
        sb[tg*VV + v] = s;
    }
    __syncthreads();
    if (tid < VV) {
        float tot = 0.f;
        #pragma unroll
        for (int tg = 0; tg < 32; tg++) tot += sb[tg*VV + tid];
        g_xbar[blk*VV + tid] = tot * (1.f / TDIM);
    }
}

// ---------------- K2: p = softmax_v(-(w2.xbar + b2)) ----------------
__global__ void k_p(const float* __restrict__ w2, const float* __restrict__ b2) {
    int blk = blockIdx.x;
    int n = blk / ICC, i = blk % ICC;
    int v = threadIdx.x;
    float val = -1e30f;
    if (v < VV) {
        float acc = b2[i];
        const float* xb = g_xbar + n*CINC*VV;
        #pragma unroll 8
        for (int c = 0; c < CINC; c++) acc += w2[i*CINC + c] * xb[c*VV + v];
        val = -acc;
    }
    float m = val;
    #pragma unroll
    for (int s = 16; s; s >>= 1) m = fmaxf(m, __shfl_xor_sync(0xffffffffu, m, s));
    float e = (v < VV) ? expf(val - m) : 0.f;
    float ssum = e;
    #pragma unroll
    for (int s = 16; s; s >>= 1) ssum += __shfl_xor_sync(0xffffffffu, ssum, s);
    if (v < VV) g_p[blk*VV + v] = e / ssum;
}

// ---------------- K3: Z = Wstack(384x64) @ x(64x6400) per n, tf32 mma ----------------
#define ZPA 68     // A pitch: banks (4g+tg)%32 distinct
#define ZPB 136    // B pitch: banks (8tg+g)%32 distinct

__global__ void __launch_bounds__(256, 2) k_zgemm(const float* __restrict__ x) {
    __shared__ float sA[128*ZPA];   // 34.8KB
    __shared__ float sB[64*ZPB];    // 34.8KB
    int tid = threadIdx.x, wid = tid >> 5, lane = tid & 31;
    int g = lane >> 2, tg = lane & 3;
    int warp_m = wid & 3, warp_n = wid >> 2;
    int j0 = blockIdx.x * 128;
    int m0 = blockIdx.y * 128;
    int n  = blockIdx.z;

    // fill A (pre-rounded tf32 weights)
    #pragma unroll
    for (int e = 0; e < 32; e++) {
        int idx = e*256 + tid;
        int o = idx >> 6, k = idx & 63;
        sA[o*ZPA + k] = g_wstk[(m0 + o)*CINC + k];
    }
    // fill B (x slice, rounded to tf32)
    const float* xn = x + (size_t)n * CINC * JDIM;
    #pragma unroll
    for (int e = 0; e < 32; e++) {
        int idx = e*256 + tid;
        int c = idx >> 7, j = idx & 127;
        sB[c*ZPB + j] = to_tf32(xn[(size_t)c*JDIM + j0 + j]);
    }
    __syncthreads();

    float acc[2][8][4];
    #pragma unroll
    for (int mt = 0; mt < 2; mt++)
        #pragma unroll
        for (int nt = 0; nt < 8; nt++)
            #pragma unroll
            for (int q = 0; q < 4; q++) acc[mt][nt][q] = 0.f;

    #pragma unroll
    for (int ks = 0; ks < 8; ks++) {
        int k0 = ks*8;
        uint32_t a[2][4];
        #pragma unroll
        for (int mt = 0; mt < 2; mt++) {
            int ob = warp_m*32 + mt*16;
            a[mt][0] = __float_as_uint(sA[(ob + g    )*ZPA + k0 + tg    ]);
            a[mt][1] = __float_as_uint(sA[(ob + g + 8)*ZPA + k0 + tg    ]);
            a[mt][2] = __float_as_uint(sA[(ob + g    )*ZPA + k0 + tg + 4]);
            a[mt][3] = __float_as_uint(sA[(ob + g + 8)*ZPA + k0 + tg + 4]);
        }
        #pragma unroll
        for (int nt = 0; nt < 8; nt++) {
            int tb = warp_n*64 + nt*8;
            uint32_t b0 = __float_as_uint(sB[(k0 + tg    )*ZPB + tb + g]);
            uint32_t b1 = __float_as_uint(sB[(k0 + tg + 4)*ZPB + tb + g]);
            #pragma unroll
            for (int mt = 0; mt < 2; mt++) {
                asm volatile(
                    "mma.sync.aligned.m16n8k8.row.col.f32.tf32.tf32.f32 "
                    "{%0,%1,%2,%3}, {%4,%5,%6,%7}, {%8,%9}, {%0,%1,%2,%3};"
                    : "+f"(acc[mt][nt][0]), "+f"(acc[mt][nt][1]),
                      "+f"(acc[mt][nt][2]), "+f"(acc[mt][nt][3])
                    : "r"(a[mt][0]), "r"(a[mt][1]), "r"(a[mt][2]), "r"(a[mt][3]),
                      "r"(b0), "r"(b1));
            }
        }
    }

    // store: rows m0+o, cols j0+tb (float2 pairs)
    size_t zb = ((size_t)n*384 + m0)*JDIM + j0;
    #pragma unroll
    for (int mt = 0; mt < 2; mt++) {
        int ob = warp_m*32 + mt*16;
        #pragma unroll
        for (int nt = 0; nt < 8; nt++) {
            int tl = warp_n*64 + nt*8 + 2*tg;
            *(float2*)&g_z[zb + (size_t)(ob + g    )*JDIM + tl] =
                make_float2(acc[mt][nt][0], acc[mt][nt][1]);
            *(float2*)&g_z[zb + (size_t)(ob + g + 8)*JDIM + tl] =
                make_float2(acc[mt][nt][2], acc[mt][nt][3]);
        }
    }
}

// ---------------- K3.5: A-mix + p-dot + BN1/ReLU -> g_hT ; residual -> g_rT ----------
__global__ void __launch_bounds__(256) k_amix(const float* __restrict__ A) {
    int blk = blockIdx.x;                 // n*128 + o
    int n = blk >> 7, o = blk & 127;
    __shared__ float z4s[TDIM*27];        // 27.6KB, pitch 27 (conflict-free)
    __shared__ float zrs[TDIM*27];        // 27.6KB
    __shared__ float As[VV*VV];
    __shared__ float ps[VV];
    int tid = threadIdx.x;

    const float* z3p = g_z + ((size_t)n*384 + o)*JDIM;
    const float* z4p = z3p + (size_t)128*JDIM;
    const float* zrp = z3p + (size_t)256*JDIM;
    float b4 = g_b4f[o];

    for (int idx = tid; idx < JDIM; idx += 256) {
        int t = idx / VV, v = idx - t*VV;
        z4s[t*27 + v] = z4p[idx] + b4;
        zrs[t*27 + v] = zrp[idx];
    }
    for (int idx = tid; idx < VV*VV; idx += 256) As[idx] = A[idx];
    if (tid < VV) ps[tid] = g_p[(n*ICC + (o & 31))*VV + tid];
    __syncthreads();

    int t = tid;
    float base = g_b3f[o] + g_h1[o];
    {
        const float* zrow = z3p + t*VV;
        #pragma unroll
        for (int v = 0; v < VV; v++) base += ps[v] * zrow[v];
    }
    float Cr = g_Cc[o];
    #pragma unroll
    for (int u = 0; u < VV; u++) {
        float acc = base;
        const float* Ar = &As[u*VV];
        #pragma unroll
        for (int v = 0; v < VV; v++) acc += Ar[v] * z4s[t*27 + v];
        size_t row = ((size_t)(n*VV + u)*COUTC + o)*TDIM;
        g_hT[row + t] = to_tf32(fmaxf(acc, 0.f));
        g_rT[row + t] = zrs[t*27 + u] + Cr;
    }
}

// ---------------- K4: temporal conv as warp-level tf32 mma.sync GEMM ----------------
#define NCHUNK 72
#define KC 16
#define PA 20
#define PB 136
#define A0_OFF 0
#define A1_OFF 2560
#define B0_OFF 5120
#define B1_OFF 7296
#define SMEM_FL 9472

__global__ void __launch_bounds__(256, 2) k_mma() {
    __shared__ float smem_all[SMEM_FL];
    int tid = threadIdx.x, wid = tid >> 5, lane = tid & 31;
    int g = lane >> 2, tg = lane & 3;
    int warp_m = wid & 3, warp_n = wid >> 2;
    int t0 = blockIdx.x * 128;
    int u  = blockIdx.y;
    int n  = blockIdx.z;

    uint32_t sbase = smem_u32(smem_all);
    const float* hrow = g_hT + (((size_t)n*VV + u)*COUTC)*TDIM;

    float acc[2][8][4];
    #pragma unroll
    for (int mt = 0; mt < 2; mt++)
        #pragma unroll
        for (int nt = 0; nt < 8; nt++)
            #pragma unroll
            for (int q = 0; q < 4; q++) acc[mt][nt][q] = 0.f;

    auto fill = [&](int c, int buf) {
        uint32_t sa = sbase + (buf ? A1_OFF : A0_OFF) * 4;
        #pragma unroll
        for (int e = 0; e < 8; e++) {
            int idx = e*256 + tid;
            int o = idx >> 4, j = idx & 15;
            uint32_t dst = sa + (o*PA + j)*4;
            const float* src = g_wt2 + o*1152 + c*KC + j;
            asm volatile("cp.async.ca.shared.global [%0], [%1], 4;" :: "r"(dst), "l"(src));
        }
        uint32_t sb = sbase + (buf ? B1_OFF : B0_OFF) * 4;
        #pragma unroll
        for (int e = 0; e < 8; e++) {
            int idx = e*256 + tid;
            int j = idx >> 7, t = idx & 127;
            int kk = c*KC + j;
            int i = kk / 9, k = kk - i*9;
            int tgi = t0 + t + k - 4;
            int inr = (tgi >= 0 && tgi < TDIM) ? 4 : 0;
            int tcl = min(max(tgi, 0), TDIM - 1);
            const float* src = hrow + (size_t)i*TDIM + tcl;
            uint32_t dst = sb + (j*PB + t)*4;
            asm volatile("cp.async.ca.shared.global [%0], [%1], 4, %2;"
                         :: "r"(dst), "l"(src), "r"(inr));
        }
        asm volatile("cp.async.commit_group;" ::: "memory");
    };

    fill(0, 0);
    for (int c = 0; c < NCHUNK; c++) {
        asm volatile("cp.async.wait_group 0;" ::: "memory");
        __syncthreads();
        if (c + 1 < NCHUNK) fill(c + 1, (c + 1) & 1);

        const float* sA = smem_all + ((c & 1) ? A1_OFF : A0_OFF);
        const float* sB = smem_all + ((c & 1) ? B1_OFF : B0_OFF);
        #pragma unroll
        for (int ks = 0; ks < 2; ks++) {
            int k0 = ks*8;
            uint32_t a[2][4];
            #pragma unroll
            for (int mt = 0; mt < 2; mt++) {
                int ob = warp_m*32 + mt*16;
                a[mt][0] = __float_as_uint(sA[(ob + g    )*PA + k0 + tg    ]);
                a[mt][1] = __float_as_uint(sA[(ob + g + 8)*PA + k0 + tg    ]);
                a[mt][2] = __float_as_uint(sA[(ob + g    )*PA + k0 + tg + 4]);
                a[mt][3] = __float_as_uint(sA[(ob + g + 8)*PA + k0 + tg + 4]);
            }
            #pragma unroll
            for (int nt = 0; nt < 8; nt++) {
                int tb = warp_n*64 + nt*8;
                uint32_t b0 = __float_as_uint(sB[(k0 + tg    )*PB + tb + g]);
                uint32_t b1 = __float_as_uint(sB[(k0 + tg + 4)*PB + tb + g]);
                #pragma unroll
                for (int mt = 0; mt < 2; mt++) {
                    asm volatile(
                        "mma.sync.aligned.m16n8k8.row.col.f32.tf32.tf32.f32 "
                        "{%0,%1,%2,%3}, {%4,%5,%6,%7}, {%8,%9}, {%0,%1,%2,%3};"
                        : "+f"(acc[mt][nt][0]), "+f"(acc[mt][nt][1]),
                          "+f"(acc[mt][nt][2]), "+f"(acc[mt][nt][3])
                        : "r"(a[mt][0]), "r"(a[mt][1]), "r"(a[mt][2]), "r"(a[mt][3]),
                          "r"(b0), "r"(b1));
                }
            }
        }
    }

    // Epilogue: acc -> stage smem -> +residual, ReLU -> g_y (t-contiguous)
    float* stage = smem_all;
    size_t yb = (((size_t)n*VV + u)*COUTC)*TDIM + t0;
    #pragma unroll
    for (int rr = 0; rr < 2; rr++) {
        __syncthreads();
        if (warp_n == rr) {
            #pragma unroll
            for (int mt = 0; mt < 2; mt++) {
                int o = warp_m*32 + mt*16 + g;
                #pragma unroll
                for (int nt = 0; nt < 8; nt++) {
                    int tl = nt*8 + 2*tg;
                    stage[ o     *68 + tl    ] = acc[mt][nt][0];
                    stage[ o     *68 + tl + 1] = acc[mt][nt][1];
                    stage[(o + 8)*68 + tl    ] = acc[mt][nt][2];
                    stage[(o + 8)*68 + tl + 1] = acc[mt][nt][3];
                }
            }
        }
        __syncthreads();
        #pragma unroll
        for (int e = 0; e < 32; e++) {
            int idx = e*256 + tid;            // 128*64
            int o = idx >> 6, tl = idx & 63;
            size_t gi = yb + (size_t)o*TDIM + rr*64 + tl;
            g_y[gi] = fmaxf(stage[o*68 + tl] + g_rT[gi], 0.f);
        }
    }
}

// ---------------- K5: pure transpose g_y -> out [n][o][t][u] ----------------
__global__ void __launch_bounds__(256) k_out(float* __restrict__ out) {
    int blk = blockIdx.x;                  // n*128 + o
    int n = blk >> 7, o = blk & 127;
    __shared__ float sy[TDIM * 27];
    int tid = threadIdx.x;
    size_t ybase = (((size_t)n*VV)*COUTC + o)*TDIM;
    #pragma unroll
    for (int u = 0; u < VV; u++) {
        sy[tid*27 + u] = g_y[ybase + (size_t)u*COUTC*TDIM + tid];
    }
    __syncthreads();
    size_t ob = ((size_t)n*COUTC + o) * TDIM * VV;
    for (int idx = tid; idx < TDIM*VV; idx += 256) {
        int t = idx / VV, u = idx - VV*t;
        out[ob + idx] = sy[t*27 + u];
    }
}

// ---------------- launch ----------------
extern "C" void kernel_launch(void* const* d_in, const int* in_sizes, int n_in,
                              void* d_out, int out_size) {
    const float* x     = (const float*)d_in[0];
    const float* A     = (const float*)d_in[1];
    const float* w2    = (const float*)d_in[4];
    const float* b2    = (const float*)d_in[5];
    const float* w3    = (const float*)d_in[6];
    const float* b3    = (const float*)d_in[7];
    const float* w4    = (const float*)d_in[8];
    const float* b4    = (const float*)d_in[9];
    const float* bn1_g = (const float*)d_in[10];
    const float* bn1_b = (const float*)d_in[11];
    const float* bn1_m = (const float*)d_in[12];
    const float* bn1_v = (const float*)d_in[13];
    const float* wt    = (const float*)d_in[14];
    const float* bt    = (const float*)d_in[15];
    const float* bn2_g = (const float*)d_in[16];
    const float* bn2_b = (const float*)d_in[17];
    const float* bn2_m = (const float*)d_in[18];
    const float* bn2_v = (const float*)d_in[19];
    const float* wr    = (const float*)d_in[20];
    const float* br    = (const float*)d_in[21];
    const float* bnr_g = (const float*)d_in[22];
    const float* bnr_b = (const float*)d_in[23];
    const float* bnr_m = (const float*)d_in[24];
    const float* bnr_v = (const float*)d_in[25];
    float* out = (float*)d_out;

    k_fold<<<(COUTC*COUTC*9 + 255)/256, 256>>>(w3, b3, w4, b4,
                                               bn1_g, bn1_b, bn1_m, bn1_v,
                                               wt, bt, bn2_g, bn2_b, bn2_m, bn2_v,
                                               wr, br, bnr_g, bnr_b, bnr_m, bnr_v);
    k_xbar<<<NB*CINC, 800>>>(x);
    k_p<<<NB*ICC, 32>>>(w2, b2);
    k_zgemm<<<dim3(JDIM/128, 3, NB), 256>>>(x);
    k_amix<<<NB*COUTC, 256>>>(A);
    k_mma<<<dim3(2, VV, NB), 256>>>();
    k_out<<<NB*COUTC, 256>>>(out);
}

// round 11
// speedup vs baseline: 5.8153x; 1.3670x over previous
#include <cuda_runtime.h>
#include <cstdint>

#define NB   32
#define CINC 64
#define COUTC 128
#define TDIM 256
#define VV   25
#define ICC  32
#define EPSB 1e-5f
#define JD   6400            // t*v columns per (n, channel)

// ---------------- scratch (device globals, no allocation) ----------------
__device__ float g_xT[(size_t)NB*CINC*VV*TDIM];     // tf32 x, [n][c][v][t]
__device__ float g_z[(size_t)NB*256*VV*TDIM];       // z3(0..127), z4(128..255): [n][o'][v][t]
__device__ float g_rT[(size_t)NB*VV*COUTC*TDIM];    // residual + consts, [n][v][o][t]
__device__ float g_hTp[(size_t)NB*VV*COUTC*264];    // padded h rows: [n][u][o][(4+256+4)]
__device__ float g_y[(size_t)NB*VV*COUTC*TDIM];     // final (y+r, relu), [n][u][o][t]
__device__ float g_xbar[NB*CINC*VV];
__device__ float g_p[NB*ICC*VV];
__device__ float g_wstk[384*CINC];                  // [w3*s1; w4*s1; wr*sr], tf32
__device__ float g_b3f[COUTC];
__device__ float g_b4f[COUTC];
__device__ float g_h1[COUTC];
__device__ float g_Cc[COUTC];
__device__ float g_wt2T[1152*COUTC];                // wt*s2 transposed [kk][o], tf32

// ---------------- helpers ----------------
__device__ __forceinline__ float to_tf32(float x) {
    uint32_t r;
    asm("cvt.rna.tf32.f32 %0, %1;" : "=r"(r) : "f"(x));
    return __uint_as_float(r);
}
__device__ __forceinline__ uint32_t smem_u32(const void* p) {
    uint32_t a;
    asm("{ .reg .u64 t; cvta.to.shared.u64 t, %1; cvt.u32.u64 %0, t; }" : "=r"(a) : "l"(p));
    return a;
}

// ---------------- K0: BN folding + weight stack + wt transpose ----------------
__global__ void k_fold(const float* __restrict__ w3, const float* __restrict__ b3,
                       const float* __restrict__ w4, const float* __restrict__ b4,
                       const float* __restrict__ bn1_g, const float* __restrict__ bn1_b,
                       const float* __restrict__ bn1_m, const float* __restrict__ bn1_v,
                       const float* __restrict__ wt,  const float* __restrict__ bt,
                       const float* __restrict__ bn2_g, const float* __restrict__ bn2_b,
                       const float* __restrict__ bn2_m, const float* __restrict__ bn2_v,
                       const float* __restrict__ wr,  const float* __restrict__ br,
                       const float* __restrict__ bnr_g, const float* __restrict__ bnr_b,
                       const float* __restrict__ bnr_m, const float* __restrict__ bnr_v) {
    int idx = blockIdx.x * blockDim.x + threadIdx.x;
    if (idx < COUTC*COUTC*9) {
        int o = idx / 1152, kk = idx - o*1152;
        float s2 = bn2_g[o] * rsqrtf(bn2_v[o] + EPSB);
        g_wt2T[kk*COUTC + o] = to_tf32(wt[idx] * s2);
    }
    if (idx < 384*CINC) {
        int op = idx >> 6, c = idx & 63;
        float w, s;
        if (op < 128) {
            s = bn1_g[op] * rsqrtf(bn1_v[op] + EPSB);
            w = w3[op*CINC + c];
        } else if (op < 256) {
            int o = op - 128;
            s = bn1_g[o] * rsqrtf(bn1_v[o] + EPSB);
            w = w4[o*CINC + c];
        } else {
            int o = op - 256;
            s = bnr_g[o] * rsqrtf(bnr_v[o] + EPSB);
            w = wr[o*CINC + c];
        }
        g_wstk[idx] = to_tf32(w * s);
    }
    if (idx < COUTC) {
        int o = idx;
        float s1 = bn1_g[o] * rsqrtf(bn1_v[o] + EPSB);
        float s2 = bn2_g[o] * rsqrtf(bn2_v[o] + EPSB);
        float sr = bnr_g[o] * rsqrtf(bnr_v[o] + EPSB);
        float h1 = bn1_b[o] - bn1_m[o]*s1;
        float h2 = bn2_b[o] - bn2_m[o]*s2;
        float hr = bnr_b[o] - bnr_m[o]*sr;
        g_b3f[o] = b3[o]*s1;
        g_b4f[o] = b4[o]*s1;
        g_h1[o]  = h1;
        g_Cc[o]  = br[o]*sr + hr + bt[o]*s2 + h2;
    }
}

// ---------------- K0.5: transpose x -> g_xT [n][c][v][t], tf32-rounded ----------------
__global__ void __launch_bounds__(256) k_xT(const float* __restrict__ x) {
    int blk = blockIdx.x;                 // n*64 + c
    __shared__ float s[VV * 257];
    const float* src = x + (size_t)blk * JD;
    int tid = threadIdx.x;
    for (int idx = tid; idx < JD; idx += 256) {
        int t = idx / VV, v = idx - VV*t;
        s[v*257 + t] = src[idx];
    }
    __syncthreads();
    float* dst = g_xT + (size_t)blk * (VV*TDIM);
    #pragma unroll
    for (int v = 0; v < VV; v++) {
        dst[v*TDIM + tid] = to_tf32(s[v*257 + tid]);
    }
}

// ---------------- K1: xbar = mean_t x ----------------
__global__ void k_xbar(const float* __restrict__ x) {
    int blk = blockIdx.x;
    __shared__ float sb[32*VV];
    int tid = threadIdx.x;
    if (tid < 800) {
        int v = tid % VV, tg = tid / VV;
        const float* xp = x + (size_t)blk * JD;
        float s = 0.f;
        for (int t = tg; t < TDIM; t += 32) s += xp[t*VV + v];
        sb[tg*VV + v] = s;
    }
    __syncthreads();
    if (tid < VV) {
        float tot = 0.f;
        #pragma unroll
        for (int tg = 0; tg < 32; tg++) tot += sb[tg*VV + tid];
        g_xbar[blk*VV + tid] = tot * (1.f / TDIM);
    }
}

// ---------------- K2: p = softmax_v(-(w2.xbar + b2)) ----------------
__global__ void k_p(const float* __restrict__ w2, const float* __restrict__ b2) {
    int blk = blockIdx.x;
    int n = blk / ICC, i = blk % ICC;
    int v = threadIdx.x;
    float val = -1e30f;
    if (v < VV) {
        float acc = b2[i];
        const float* xb = g_xbar + n*CINC*VV;
        #pragma unroll 8
        for (int c = 0; c < CINC; c++) acc += w2[i*CINC + c] * xb[c*VV + v];
        val = -acc;
    }
    float m = val;
    #pragma unroll
    for (int s = 16; s; s >>= 1) m = fmaxf(m, __shfl_xor_sync(0xffffffffu, m, s));
    float e = (v < VV) ? expf(val - m) : 0.f;
    float ssum = e;
    #pragma unroll
    for (int s = 16; s; s >>= 1) ssum += __shfl_xor_sync(0xffffffffu, ssum, s);
    if (v < VV) g_p[blk*VV + v] = e / ssum;
}

// ---------------- K3: Z = Wstack(384x64) @ xT(64 x [v][t]) per n, tf32 mma ----------
#define ZPA 68     // [o][k]: banks 4g+tg distinct
#define ZPB 136    // [k][t]: banks 8tg+g distinct

__global__ void __launch_bounds__(256, 2) k_zgemm() {
    __shared__ float sA[128*ZPA];
    __shared__ float sB[64*ZPB];
    __shared__ float ccs[COUTC];
    int tid = threadIdx.x, wid = tid >> 5, lane = tid & 31;
    int g = lane >> 2, tg = lane & 3;
    int warp_m = wid & 3, warp_n = wid >> 2;
    int jb = blockIdx.x;                 // 0..49
    int v  = jb >> 1, t0 = (jb & 1) * 128;
    int mg = blockIdx.y;                 // 0:z3 1:z4 2:zr
    int m0 = mg * 128;
    int n  = blockIdx.z;

    // fill A (tf32 weights), float4
    #pragma unroll
    for (int e = 0; e < 8; e++) {
        int i4 = e*256 + tid;
        int o = i4 >> 4, k4 = (i4 & 15) * 4;
        *(float4*)&sA[o*ZPA + k4] = *(const float4*)&g_wstk[(m0 + o)*CINC + k4];
    }
    // fill B from xT, float4
    #pragma unroll
    for (int e = 0; e < 8; e++) {
        int i4 = e*256 + tid;
        int c = i4 >> 5, t4 = (i4 & 31) * 4;
        *(float4*)&sB[c*ZPB + t4] =
            *(const float4*)&g_xT[(((size_t)n*CINC + c)*VV + v)*TDIM + t0 + t4];
    }
    if (mg == 2 && tid < COUTC) ccs[tid] = g_Cc[tid];
    __syncthreads();

    float acc[2][8][4];
    #pragma unroll
    for (int mt = 0; mt < 2; mt++)
        #pragma unroll
        for (int nt = 0; nt < 8; nt++)
            #pragma unroll
            for (int q = 0; q < 4; q++) acc[mt][nt][q] = 0.f;

    #pragma unroll
    for (int ks = 0; ks < 8; ks++) {
        int k0 = ks*8;
        uint32_t a[2][4];
        #pragma unroll
        for (int mt = 0; mt < 2; mt++) {
            int ob = warp_m*32 + mt*16;
            a[mt][0] = __float_as_uint(sA[(ob + g    )*ZPA + k0 + tg    ]);
            a[mt][1] = __float_as_uint(sA[(ob + g + 8)*ZPA + k0 + tg    ]);
            a[mt][2] = __float_as_uint(sA[(ob + g    )*ZPA + k0 + tg + 4]);
            a[mt][3] = __float_as_uint(sA[(ob + g + 8)*ZPA + k0 + tg + 4]);
        }
        #pragma unroll
        for (int nt = 0; nt < 8; nt++) {
            int tb = warp_n*64 + nt*8;
            uint32_t b0 = __float_as_uint(sB[(k0 + tg    )*ZPB + tb + g]);
            uint32_t b1 = __float_as_uint(sB[(k0 + tg + 4)*ZPB + tb + g]);
            #pragma unroll
            for (int mt = 0; mt < 2; mt++) {
                asm volatile(
                    "mma.sync.aligned.m16n8k8.row.col.f32.tf32.tf32.f32 "
                    "{%0,%1,%2,%3}, {%4,%5,%6,%7}, {%8,%9}, {%0,%1,%2,%3};"
                    : "+f"(acc[mt][nt][0]), "+f"(acc[mt][nt][1]),
                      "+f"(acc[mt][nt][2]), "+f"(acc[mt][nt][3])
                    : "r"(a[mt][0]), "r"(a[mt][1]), "r"(a[mt][2]), "r"(a[mt][3]),
                      "r"(b0), "r"(b1));
            }
        }
    }

    if (mg < 2) {
        // z layout [n][o'][v][t], o' row stride = VV*TDIM = 6400
        size_t zb = (size_t)n*(256*JD) + (size_t)m0*JD + (size_t)v*TDIM + t0;
        #pragma unroll
        for (int mt = 0; mt < 2; mt++) {
            int ob = warp_m*32 + mt*16;
            #pragma unroll
            for (int nt = 0; nt < 8; nt++) {
                int tl = warp_n*64 + nt*8 + 2*tg;
                *(float2*)&g_z[zb + (size_t)(ob + g    )*JD + tl] =
                    make_float2(acc[mt][nt][0], acc[mt][nt][1]);
                *(float2*)&g_z[zb + (size_t)(ob + g + 8)*JD + tl] =
                    make_float2(acc[mt][nt][2], acc[mt][nt][3]);
            }
        }
    } else {
        // residual: g_rT[n][v][o][t] = zr + Cc
        size_t rb = (((size_t)n*VV + v)*COUTC)*TDIM + t0;
        #pragma unroll
        for (int mt = 0; mt < 2; mt++) {
            int ob = warp_m*32 + mt*16;
            #pragma unroll
            for (int nt = 0; nt < 8; nt++) {
                int tl = warp_n*64 + nt*8 + 2*tg;
                float c0 = ccs[ob + g], c1 = ccs[ob + g + 8];
                *(float2*)&g_rT[rb + (size_t)(ob + g    )*TDIM + tl] =
                    make_float2(acc[mt][nt][0] + c0, acc[mt][nt][1] + c0);
                *(float2*)&g_rT[rb + (size_t)(ob + g + 8)*TDIM + tl] =
                    make_float2(acc[mt][nt][2] + c1, acc[mt][nt][3] + c1);
            }
        }
    }
}

// ---------------- K3.5: p-dot + A-mix + BN1/ReLU -> g_hTp (padded rows) ----------
__global__ void __launch_bounds__(256) k_amix(const float* __restrict__ A) {
    int blk = blockIdx.x;                 // n*128 + o
    int n = blk >> 7, o = blk & 127;
    __shared__ float As[VV*VV];
    __shared__ float ps[VV];
    int tid = threadIdx.x;                // = t

    for (int idx = tid; idx < VV*VV; idx += 256) As[idx] = A[idx];
    if (tid < VV) ps[tid] = g_p[(n*ICC + (o & 31))*VV + tid];
    __syncthreads();

    const float* z3p = g_z + (size_t)n*(256*JD) + (size_t)o*JD;
    const float* z4p = z3p + (size_t)128*JD;
    float b4 = g_b4f[o];
    float base = g_b3f[o] + g_h1[o];
    float z4r[VV];
    #pragma unroll
    for (int v = 0; v < VV; v++) {
        base += ps[v] * z3p[v*TDIM + tid];
        z4r[v] = z4p[v*TDIM + tid] + b4;
    }

    size_t hb = ((size_t)(n*VV)*COUTC + o)*264;     // + u*(128*264)
    #pragma unroll 1
    for (int u = 0; u < VV; u++) {
        float acc = base;
        const float* Ar = &As[u*VV];
        #pragma unroll
        for (int v = 0; v < VV; v++) acc += Ar[v] * z4r[v];
        size_t row = hb + (size_t)u*(COUTC*264);
        g_hTp[row + 4 + tid] = to_tf32(fmaxf(acc, 0.f));
        if (tid < 4) { g_hTp[row + tid] = 0.f; g_hTp[row + 260 + tid] = 0.f; }
    }
}

// ---------------- K4: temporal conv GEMM, KC=8, 4-stage A + 6-row H ring ----------
#define NCH 144
#define MPA 136        // A [j][o] pitch: banks 8tg+g distinct
#define ASTG (8*MPA)   // 1088 floats per A stage
#define SH_OFF (4*ASTG)  // 4352
#define SHP 264        // ring row pitch (136 used)
#define SMEM_FL (COUTC*68)  // 8704: epilogue stage dominates

__global__ void __launch_bounds__(256, 2) k_mma() {
    __shared__ float sm[SMEM_FL];
    int tid = threadIdx.x, wid = tid >> 5, lane = tid & 31;
    int g = lane >> 2, tg = lane & 3;
    int warp_m = wid & 3, warp_n = wid >> 2;
    int t0 = blockIdx.x * 128;
    int u  = blockIdx.y;
    int n  = blockIdx.z;
    uint32_t sb = smem_u32(sm);
    const float* hrow = g_hTp + ((size_t)(n*VV + u)*COUTC)*264;   // + i*264 (+t0)

    float acc[2][8][4];
    #pragma unroll
    for (int mt = 0; mt < 2; mt++)
        #pragma unroll
        for (int nt = 0; nt < 8; nt++)
            #pragma unroll
            for (int q = 0; q < 4; q++) acc[mt][nt][q] = 0.f;

    int next_row = 0;
    auto issue = [&](int c) {
        {   // A chunk c -> stage c&3 : one 16B cp.async per thread
            int j = tid >> 5, o4 = (tid & 31) * 4;
            uint32_t dst = sb + (((c & 3)*ASTG) + j*MPA + o4) * 4;
            const float* src = g_wt2T + (size_t)(c*8 + j)*COUTC + o4;
            asm volatile("cp.async.ca.shared.global [%0], [%1], 16;" :: "r"(dst), "l"(src));
        }
        int imax = (8*c + 7) / 9;
        while (next_row <= imax) {
            if (tid < 34) {
                int slot = next_row % 6;
                uint32_t dst = sb + (SH_OFF + slot*SHP + tid*4) * 4;
                const float* src = hrow + (size_t)next_row*264 + t0 + tid*4;
                asm volatile("cp.async.ca.shared.global [%0], [%1], 16;" :: "r"(dst), "l"(src));
            }
            next_row++;
        }
        asm volatile("cp.async.commit_group;" ::: "memory");
    };

    issue(0); issue(1); issue(2);
    for (int c = 0; c < NCH; c++) {
        asm volatile("cp.async.wait_group 2;" ::: "memory");
        __syncthreads();
        if (c + 3 < NCH) issue(c + 3);
        else asm volatile("cp.async.commit_group;" ::: "memory");

        const float* sA = sm + (c & 3)*ASTG;
        uint32_t a[2][4];
        #pragma unroll
        for (int mt = 0; mt < 2; mt++) {
            int ob = warp_m*32 + mt*16;
            a[mt][0] = __float_as_uint(sA[ tg     *MPA + ob + g    ]);
            a[mt][1] = __float_as_uint(sA[ tg     *MPA + ob + g + 8]);
            a[mt][2] = __float_as_uint(sA[(tg + 4)*MPA + ob + g    ]);
            a[mt][3] = __float_as_uint(sA[(tg + 4)*MPA + ob + g + 8]);
        }
        int kb0 = c*8 + tg, kb1 = kb0 + 4;
        int i0 = (kb0 * 7282) >> 16; int k0 = kb0 - 9*i0;
        int i1 = (kb1 * 7282) >> 16; int k1 = kb1 - 9*i1;
        const float* h0 = sm + SH_OFF + (i0 % 6)*SHP + k0 + g;
        const float* h1 = sm + SH_OFF + (i1 % 6)*SHP + k1 + g;
        #pragma unroll
        for (int nt = 0; nt < 8; nt++) {
            int tb = warp_n*64 + nt*8;
            uint32_t b0 = __float_as_uint(h0[tb]);
            uint32_t b1 = __float_as_uint(h1[tb]);
            #pragma unroll
            for (int mt = 0; mt < 2; mt++) {
                asm volatile(
                    "mma.sync.aligned.m16n8k8.row.col.f32.tf32.tf32.f32 "
                    "{%0,%1,%2,%3}, {%4,%5,%6,%7}, {%8,%9}, {%0,%1,%2,%3};"
                    : "+f"(acc[mt][nt][0]), "+f"(acc[mt][nt][1]),
                      "+f"(acc[mt][nt][2]), "+f"(acc[mt][nt][3])
                    : "r"(a[mt][0]), "r"(a[mt][1]), "r"(a[mt][2]), "r"(a[mt][3]),
                      "r"(b0), "r"(b1));
            }
        }
    }

    // Epilogue: acc -> stage -> (+rT, ReLU) -> g_y, float4
    float* stage = sm;
    size_t yb = (((size_t)n*VV + u)*COUTC)*TDIM + t0;
    #pragma unroll
    for (int rr = 0; rr < 2; rr++) {
        __syncthreads();
        if (warp_n == rr) {
            #pragma unroll
            for (int mt = 0; mt < 2; mt++) {
                int o = warp_m*32 + mt*16 + g;
                #pragma unroll
                for (int nt = 0; nt < 8; nt++) {
                    int tl = nt*8 + 2*tg;
                    stage[ o     *68 + tl    ] = acc[mt][nt][0];
                    stage[ o     *68 + tl + 1] = acc[mt][nt][1];
                    stage[(o + 8)*68 + tl    ] = acc[mt][nt][2];
                    stage[(o + 8)*68 + tl + 1] = acc[mt][nt][3];
                }
            }
        }
        __syncthreads();
        #pragma unroll
        for (int e = 0; e < 8; e++) {
            int i4 = e*256 + tid;            // 2048 float4 = 128 o x 64 t
            int o = i4 >> 4, tl = (i4 & 15) * 4;
            size_t gi = yb + (size_t)o*TDIM + rr*64 + tl;
            float4 sv = *(float4*)&stage[o*68 + tl];
            float4 rv = *(const float4*)&g_rT[gi];
            sv.x = fmaxf(sv.x + rv.x, 0.f);
            sv.y = fmaxf(sv.y + rv.y, 0.f);
            sv.z = fmaxf(sv.z + rv.z, 0.f);
            sv.w = fmaxf(sv.w + rv.w, 0.f);
            *(float4*)&g_y[gi] = sv;
        }
    }
}

// ---------------- K5: pure transpose g_y -> out [n][o][t][u] ----------------
__global__ void __launch_bounds__(256) k_out(float* __restrict__ out) {
    int blk = blockIdx.x;                  // n*128 + o
    int n = blk >> 7, o = blk & 127;
    __shared__ float sy[TDIM * 27];
    int tid = threadIdx.x;
    size_t ybase = (((size_t)n*VV)*COUTC + o)*TDIM;
    #pragma unroll
    for (int u = 0; u < VV; u++) {
        sy[tid*27 + u] = g_y[ybase + (size_t)u*COUTC*TDIM + tid];
    }
    __syncthreads();
    size_t ob = ((size_t)n*COUTC + o) * (size_t)JD;
    for (int idx = tid; idx < JD; idx += 256) {
        int t = idx / VV, u = idx - VV*t;
        out[ob + idx] = sy[t*27 + u];
    }
}

// ---------------- launch ----------------
extern "C" void kernel_launch(void* const* d_in, const int* in_sizes, int n_in,
                              void* d_out, int out_size) {
    const float* x     = (const float*)d_in[0];
    const float* A     = (const float*)d_in[1];
    const float* w2    = (const float*)d_in[4];
    const float* b2    = (const float*)d_in[5];
    const float* w3    = (const float*)d_in[6];
    const float* b3    = (const float*)d_in[7];
    const float* w4    = (const float*)d_in[8];
    const float* b4    = (const float*)d_in[9];
    const float* bn1_g = (const float*)d_in[10];
    const float* bn1_b = (const float*)d_in[11];
    const float* bn1_m = (const float*)d_in[12];
    const float* bn1_v = (const float*)d_in[13];
    const float* wt    = (const float*)d_in[14];
    const float* bt    = (const float*)d_in[15];
    const float* bn2_g = (const float*)d_in[16];
    const float* bn2_b = (const float*)d_in[17];
    const float* bn2_m = (const float*)d_in[18];
    const float* bn2_v = (const float*)d_in[19];
    const float* wr    = (const float*)d_in[20];
    const float* br    = (const float*)d_in[21];
    const float* bnr_g = (const float*)d_in[22];
    const float* bnr_b = (const float*)d_in[23];
    const float* bnr_m = (const float*)d_in[24];
    const float* bnr_v = (const float*)d_in[25];
    float* out = (float*)d_out;

    k_fold<<<(COUTC*COUTC*9 + 255)/256, 256>>>(w3, b3, w4, b4,
                                               bn1_g, bn1_b, bn1_m, bn1_v,
                                               wt, bt, bn2_g, bn2_b, bn2_m, bn2_v,
                                               wr, br, bnr_g, bnr_b, bnr_m, bnr_v);
    k_xT<<<NB*CINC, 256>>>(x);
    k_xbar<<<NB*CINC, 800>>>(x);
    k_p<<<NB*ICC, 32>>>(w2, b2);
    k_zgemm<<<dim3(50, 3, NB), 256>>>();
    k_amix<<<NB*COUTC, 256>>>(A);
    k_mma<<<dim3(2, VV, NB), 256>>>();
    k_out<<<NB*COUTC, 256>>>(out);
}